// round 5
// baseline (speedup 1.0000x reference)
#include <cuda_runtime.h>
#include <math.h>
#include <stdint.h>

#define BB 8
#define LL 4096
#define DD 1024
#define MM (BB * LL)          // 32768 rows
#define DD2 (2 * DD)          // 2048
#define NCH 32
#define CHUNK (LL / NCH)      // 128

// ---------------- scratch (device globals; no allocation allowed) ----------
__device__ float g_avg[(size_t)MM * DD];      // cumulative mean (full fp32)
__device__ float g_h[(size_t)MM * DD];        // layernorm(avg), tf32-rounded
__device__ float g_inter[(size_t)MM * DD];    // relu(h@w1+b1), tf32-rounded
__device__ float g_avgout[(size_t)MM * DD];   // inter@w2+b2+avg (full fp32)
__device__ float g_avgout_r[(size_t)MM * DD]; // tf32-rounded copy
__device__ float g_in_r[(size_t)MM * DD];     // tf32-rounded inputs
__device__ float g_csum[BB * NCH * DD];       // chunk partial sums
__device__ float g_w1t[DD * DD];              // w1^T [N][K], tf32-rounded
__device__ float g_w2t[DD * DD];
__device__ float g_wgt[(size_t)DD2 * DD2];

// ---------------- helpers ----------------------------------------------------
__device__ __forceinline__ float f2tf32f(float x) {
    uint32_t r;
    asm("cvt.rna.tf32.f32 %0, %1;" : "=r"(r) : "f"(x));
    return __uint_as_float(r);
}
__device__ __forceinline__ float sigf(float x) { return 1.f / (1.f + expf(-x)); }

#define CP_ASYNC16(dst, src) \
    asm volatile("cp.async.cg.shared.global [%0], [%1], 16;" \
                 :: "r"(dst), "l"(src) : "memory")
#define CP_COMMIT() asm volatile("cp.async.commit_group;" ::: "memory")

#define MMA_TF32(c, a0, a1, a2, a3, b0, b1)                                   \
    asm volatile(                                                             \
        "mma.sync.aligned.m16n8k8.row.col.f32.tf32.tf32.f32 "                 \
        "{%0,%1,%2,%3}, {%4,%5,%6,%7}, {%8,%9}, {%0,%1,%2,%3};"               \
        : "+f"((c)[0]), "+f"((c)[1]), "+f"((c)[2]), "+f"((c)[3])              \
        : "r"(a0), "r"(a1), "r"(a2), "r"(a3), "r"(b0), "r"(b1))

// ---------------- phase 1: chunked cumulative sum --------------------------
__global__ void __launch_bounds__(256) k_chunksum(const float* __restrict__ in) {
    int idx = blockIdx.x * blockDim.x + threadIdx.x;
    int d = idx & (DD - 1);
    int chunk = (idx >> 10) & (NCH - 1);
    int b = idx >> 15;
    const float* p = in + ((size_t)(b * LL + chunk * CHUNK)) * DD + d;
    float s = 0.f;
#pragma unroll 4
    for (int l = 0; l < CHUNK; ++l) s += p[(size_t)l * DD];
    g_csum[(b * NCH + chunk) * DD + d] = s;
}

__global__ void __launch_bounds__(256) k_scan() {
    int idx = blockIdx.x * blockDim.x + threadIdx.x;
    int d = idx & (DD - 1);
    int b = idx >> 10;
    float run = 0.f;
#pragma unroll
    for (int c = 0; c < NCH; ++c) {
        int o = (b * NCH + c) * DD + d;
        float t = g_csum[o];
        g_csum[o] = run;
        run += t;
    }
}

__global__ void __launch_bounds__(256) k_apply(const float* __restrict__ in) {
    int idx = blockIdx.x * blockDim.x + threadIdx.x;
    int d = idx & (DD - 1);
    int chunk = (idx >> 10) & (NCH - 1);
    int b = idx >> 15;
    size_t base = ((size_t)(b * LL + chunk * CHUNK)) * DD + d;
    const float* p = in + base;
    float* q = g_avg + base;
    float* qr = g_in_r + base;
    float run = g_csum[(b * NCH + chunk) * DD + d];
    int l0 = chunk * CHUNK;
#pragma unroll 4
    for (int l = 0; l < CHUNK; ++l) {
        float v = p[(size_t)l * DD];
        run += v;
        q[(size_t)l * DD] = run / (float)(l0 + l + 1);
        qr[(size_t)l * DD] = f2tf32f(v);
    }
}

// ---------------- phase 2: layernorm over D per row (tf32-rounded out) ------
__global__ void __launch_bounds__(256) k_ln(const float* __restrict__ lng,
                                            const float* __restrict__ lnb) {
    int row = blockIdx.x;
    int t = threadIdx.x;
    const float4* x4 = reinterpret_cast<const float4*>(g_avg + (size_t)row * DD);
    float4 a = x4[t];
    float s = a.x + a.y + a.z + a.w;
    float ss = a.x * a.x + a.y * a.y + a.z * a.z + a.w * a.w;
#pragma unroll
    for (int o = 16; o > 0; o >>= 1) {
        s  += __shfl_xor_sync(0xffffffffu, s, o);
        ss += __shfl_xor_sync(0xffffffffu, ss, o);
    }
    __shared__ float sm[16];
    int w = t >> 5;
    if ((t & 31) == 0) { sm[w] = s; sm[8 + w] = ss; }
    __syncthreads();
    if (t < 32) {
        float v1 = (t < 8) ? sm[t] : 0.f;
        float v2 = (t < 8) ? sm[8 + t] : 0.f;
#pragma unroll
        for (int o = 4; o > 0; o >>= 1) {
            v1 += __shfl_xor_sync(0xffffffffu, v1, o);
            v2 += __shfl_xor_sync(0xffffffffu, v2, o);
        }
        if (t == 0) { sm[0] = v1; sm[1] = v2; }
    }
    __syncthreads();
    float mean = sm[0] * (1.f / DD);
    float var  = sm[1] * (1.f / DD) - mean * mean;
    float inv  = rsqrtf(var + 1e-6f);
    float4 g = reinterpret_cast<const float4*>(lng)[t];
    float4 b = reinterpret_cast<const float4*>(lnb)[t];
    float4 h;
    h.x = f2tf32f((a.x - mean) * inv * g.x + b.x);
    h.y = f2tf32f((a.y - mean) * inv * g.y + b.y);
    h.z = f2tf32f((a.z - mean) * inv * g.z + b.z);
    h.w = f2tf32f((a.w - mean) * inv * g.w + b.w);
    reinterpret_cast<float4*>(g_h + (size_t)row * DD)[t] = h;
}

// ---------------- weight transpose (tf32-rounded): Wt[n][k] = W[k][n] -------
__global__ void __launch_bounds__(256) k_transpose(const float* __restrict__ W,
                                                   float* __restrict__ Wt, int N) {
    __shared__ float t[32][33];
    int bx = blockIdx.x * 32, by = blockIdx.y * 32;
    int x = bx + threadIdx.x;
#pragma unroll
    for (int i = 0; i < 32; i += 8)
        t[threadIdx.y + i][threadIdx.x] = W[(size_t)(by + threadIdx.y + i) * N + x];
    __syncthreads();
    int x2 = by + threadIdx.x;
#pragma unroll
    for (int i = 0; i < 32; i += 8)
        Wt[(size_t)(bx + threadIdx.y + i) * N + x2] = f2tf32f(t[threadIdx.x][threadIdx.y + i]);
}

// ---------------- phase 3a: tf32 mma.sync GEMM (gemm1/gemm2) -----------------
// CTA tile 128x128, BK=32, 8 warps (2x4), warp tile 64x32, mma m16n8k8.
// MODE 0: round(relu(x+b))->C            (gemm1 -> inter)
// MODE 1: x+b+add->C, round(...)->C2     (gemm2 -> avgout, avgout_r)
#define LDP 36
#define STG_FLTS (2 * 128 * LDP)          // A tile + B tile per stage
#define GEMM_SMEM (2 * STG_FLTS * 4)      // 2 stages = 73728 B

template <int MODE, int KTOT, int NN>
__global__ void __launch_bounds__(256, 2) k_gemm_mma(
    const float* __restrict__ A0,
    const float* __restrict__ Wt, const float* __restrict__ bias,
    const float* __restrict__ add, float* __restrict__ C,
    float* __restrict__ C2) {
    extern __shared__ float smf[];
    int tid = threadIdx.x;
    int wid = tid >> 5, lane = tid & 31;
    int g = lane >> 2, tg = lane & 3;
    int wm = wid >> 2, wn = wid & 3;       // 2 x 4 warp grid
    int bm = blockIdx.y * 128, bn = blockIdx.x * 128;

    float acc[16][4];
#pragma unroll
    for (int i = 0; i < 16; ++i)
#pragma unroll
        for (int j = 0; j < 4; ++j) acc[i][j] = 0.f;

    int ldr = tid >> 3;                    // 0..31
    int ldc = (tid & 7) << 2;              // 0,4,...,28
    const int NK = KTOT / 32;

#define LOAD_STAGE(s, kk_)                                                     \
    {                                                                          \
        int kk = (kk_);                                                        \
        float* As = smf + (s) * STG_FLTS;                                      \
        float* Bs = As + 128 * LDP;                                            \
        _Pragma("unroll")                                                      \
        for (int it = 0; it < 4; ++it) {                                       \
            int r = ldr + it * 32;                                             \
            uint32_t da = (uint32_t)__cvta_generic_to_shared(As + r * LDP + ldc); \
            CP_ASYNC16(da, A0 + (size_t)(bm + r) * DD + kk + ldc);             \
            uint32_t db = (uint32_t)__cvta_generic_to_shared(Bs + r * LDP + ldc); \
            CP_ASYNC16(db, Wt + (size_t)(bn + r) * KTOT + kk + ldc);           \
        }                                                                      \
    }

    LOAD_STAGE(0, 0);
    CP_COMMIT();

    for (int kt = 0; kt < NK; ++kt) {
        int cur = kt & 1;
        if (kt + 1 < NK) {
            LOAD_STAGE(cur ^ 1, (kt + 1) * 32);
            CP_COMMIT();
            asm volatile("cp.async.wait_group 1;" ::: "memory");
        } else {
            asm volatile("cp.async.wait_group 0;" ::: "memory");
        }
        __syncthreads();

        const float* As = smf + cur * STG_FLTS;
        const float* Bs = As + 128 * LDP;
#pragma unroll
        for (int kc = 0; kc < 4; ++kc) {
            int kb = kc * 8;
            uint32_t af[4][4], bf[4][2];
#pragma unroll
            for (int mt = 0; mt < 4; ++mt) {
                int r0 = (wm * 64 + mt * 16 + g) * LDP + kb + tg;
                af[mt][0] = __float_as_uint(As[r0]);
                af[mt][1] = __float_as_uint(As[r0 + 8 * LDP]);
                af[mt][2] = __float_as_uint(As[r0 + 4]);
                af[mt][3] = __float_as_uint(As[r0 + 8 * LDP + 4]);
            }
#pragma unroll
            for (int nt = 0; nt < 4; ++nt) {
                int r0 = (wn * 32 + nt * 8 + g) * LDP + kb + tg;
                bf[nt][0] = __float_as_uint(Bs[r0]);
                bf[nt][1] = __float_as_uint(Bs[r0 + 4]);
            }
#pragma unroll
            for (int mt = 0; mt < 4; ++mt)
#pragma unroll
                for (int nt = 0; nt < 4; ++nt)
                    MMA_TF32(acc[mt * 4 + nt], af[mt][0], af[mt][1], af[mt][2],
                             af[mt][3], bf[nt][0], bf[nt][1]);
        }
        __syncthreads();
    }

#pragma unroll
    for (int mt = 0; mt < 4; ++mt) {
#pragma unroll
        for (int nt = 0; nt < 4; ++nt) {
            float* c = acc[mt * 4 + nt];
            int col = bn + wn * 32 + nt * 8 + 2 * tg;
            float2 bb = *reinterpret_cast<const float2*>(bias + col);
#pragma unroll
            for (int hh = 0; hh < 2; ++hh) {
                int row = bm + wm * 64 + mt * 16 + g + hh * 8;
                size_t off = (size_t)row * NN + col;
                float vx = c[hh * 2 + 0] + bb.x;
                float vy = c[hh * 2 + 1] + bb.y;
                if (MODE == 0) {
                    float2 o;
                    o.x = f2tf32f(fmaxf(vx, 0.f));
                    o.y = f2tf32f(fmaxf(vy, 0.f));
                    *reinterpret_cast<float2*>(C + off) = o;
                } else {
                    float2 ad = *reinterpret_cast<const float2*>(add + off);
                    vx += ad.x; vy += ad.y;
                    float2 o; o.x = vx; o.y = vy;
                    *reinterpret_cast<float2*>(C + off) = o;
                    float2 o2; o2.x = f2tf32f(vx); o2.y = f2tf32f(vy);
                    *reinterpret_cast<float2*>(C2 + off) = o2;
                }
            }
        }
    }
#undef LOAD_STAGE
}

// ---------------- phase 3b: fused dual-gate GEMM3 (gate-split warps) ---------
// Warps 0-7: input gate (wgt rows bn..bn+127); warps 8-15: forget gate
// (wgt rows bn+1024..). Both share the A tile. Epilogue: g2-warps store
// sig(g2)*avgout into a smem exchange buffer; g1-warps combine with
// sig(g1)*inputs and write out. Per-warp regs match the proven k_gemm_mma.
#define G3_TILE (128 * LDP)               // floats per smem tile
#define G3_STG  (3 * G3_TILE)             // A + B1 + B2 per stage
#define G3_SMEM (3 * G3_STG * 4)          // 3 stages = 165888 B
#define EXP 130                            // exchange pitch (floats)

__global__ void __launch_bounds__(512, 1) k_gemm3_fused(
    const float* __restrict__ A0,        // in_r  (k < 1024)
    const float* __restrict__ A1,        // avgout_r (k >= 1024)
    const float* __restrict__ Wt,        // wgt [2048][2048]
    const float* __restrict__ bg,
    const float* __restrict__ inputs,
    const float* __restrict__ avgout,
    float* __restrict__ out) {
    extern __shared__ float smf[];
    int tid = threadIdx.x;
    int wid = tid >> 5, lane = tid & 31;
    int g = lane >> 2, tg = lane & 3;
    int gate = wid >> 3;                   // 0: input gate, 1: forget gate
    int w8 = wid & 7;
    int wm = w8 >> 2, wn = w8 & 3;         // 2 x 4 grid per gate, tile 64x32
    int bm = blockIdx.y * 128, bn = blockIdx.x * 128;

    float acc[16][4];
#pragma unroll
    for (int i = 0; i < 16; ++i)
#pragma unroll
        for (int j = 0; j < 4; ++j) acc[i][j] = 0.f;

    const int NK = DD2 / 32;               // 64

#define G3_LOAD(s, kk_)                                                        \
    {                                                                          \
        int kk = (kk_);                                                        \
        const float* Ab; int kloc;                                             \
        if (kk >= DD) { Ab = A1; kloc = kk - DD; } else { Ab = A0; kloc = kk; }\
        float* As = smf + (s) * G3_STG;                                        \
        float* B1 = As + G3_TILE;                                              \
        float* B2 = B1 + G3_TILE;                                              \
        _Pragma("unroll")                                                      \
        for (int it = 0; it < 2; ++it) {                                       \
            int i = tid + it * 512;                                            \
            int r = i >> 3, c = (i & 7) << 2;                                  \
            uint32_t da = (uint32_t)__cvta_generic_to_shared(As + r * LDP + c);\
            CP_ASYNC16(da, Ab + (size_t)(bm + r) * DD + kloc + c);             \
            uint32_t d1 = (uint32_t)__cvta_generic_to_shared(B1 + r * LDP + c);\
            CP_ASYNC16(d1, Wt + (size_t)(bn + r) * DD2 + kk + c);              \
            uint32_t d2 = (uint32_t)__cvta_generic_to_shared(B2 + r * LDP + c);\
            CP_ASYNC16(d2, Wt + (size_t)(bn + DD + r) * DD2 + kk + c);         \
        }                                                                      \
    }

    G3_LOAD(0, 0);
    CP_COMMIT();
    G3_LOAD(1, 32);
    CP_COMMIT();

    int cur = 0;
    for (int kt = 0; kt < NK; ++kt) {
        asm volatile("cp.async.wait_group 1;" ::: "memory");
        __syncthreads();
        if (kt + 2 < NK) {
            int nxt = cur + 2; if (nxt >= 3) nxt -= 3;
            G3_LOAD(nxt, (kt + 2) * 32);
            CP_COMMIT();
        }

        const float* As = smf + cur * G3_STG;
        const float* Bs = As + G3_TILE + gate * G3_TILE;   // B1 or B2
#pragma unroll
        for (int kc = 0; kc < 4; ++kc) {
            int kb = kc * 8;
            uint32_t af[4][4], bf[4][2];
#pragma unroll
            for (int mt = 0; mt < 4; ++mt) {
                int r0 = (wm * 64 + mt * 16 + g) * LDP + kb + tg;
                af[mt][0] = __float_as_uint(As[r0]);
                af[mt][1] = __float_as_uint(As[r0 + 8 * LDP]);
                af[mt][2] = __float_as_uint(As[r0 + 4]);
                af[mt][3] = __float_as_uint(As[r0 + 8 * LDP + 4]);
            }
#pragma unroll
            for (int nt = 0; nt < 4; ++nt) {
                int r0 = (wn * 32 + nt * 8 + g) * LDP + kb + tg;
                bf[nt][0] = __float_as_uint(Bs[r0]);
                bf[nt][1] = __float_as_uint(Bs[r0 + 4]);
            }
#pragma unroll
            for (int mt = 0; mt < 4; ++mt)
#pragma unroll
                for (int nt = 0; nt < 4; ++nt)
                    MMA_TF32(acc[mt * 4 + nt], af[mt][0], af[mt][1], af[mt][2],
                             af[mt][3], bf[nt][0], bf[nt][1]);
        }
        __syncthreads();
        ++cur; if (cur >= 3) cur = 0;
    }

    // epilogue: gate2 -> smem exchange; barrier; gate1 combines + writes out
    float* ex = smf;                        // reuse pipeline smem (128 x EXP)
    if (gate == 1) {
#pragma unroll
        for (int mt = 0; mt < 4; ++mt) {
#pragma unroll
            for (int nt = 0; nt < 4; ++nt) {
                float* c = acc[mt * 4 + nt];
                int col_l = wn * 32 + nt * 8 + 2 * tg;
                float2 bb = *reinterpret_cast<const float2*>(bg + DD + bn + col_l);
#pragma unroll
                for (int hh = 0; hh < 2; ++hh) {
                    int row_l = wm * 64 + mt * 16 + g + hh * 8;
                    size_t off = (size_t)(bm + row_l) * DD + bn + col_l;
                    float2 av = *reinterpret_cast<const float2*>(avgout + off);
                    float2 v;
                    v.x = sigf(c[hh * 2 + 0] + bb.x) * av.x;
                    v.y = sigf(c[hh * 2 + 1] + bb.y) * av.y;
                    *reinterpret_cast<float2*>(ex + row_l * EXP + col_l) = v;
                }
            }
        }
    }
    __syncthreads();
    if (gate == 0) {
#pragma unroll
        for (int mt = 0; mt < 4; ++mt) {
#pragma unroll
            for (int nt = 0; nt < 4; ++nt) {
                float* c = acc[mt * 4 + nt];
                int col_l = wn * 32 + nt * 8 + 2 * tg;
                float2 bb = *reinterpret_cast<const float2*>(bg + bn + col_l);
#pragma unroll
                for (int hh = 0; hh < 2; ++hh) {
                    int row_l = wm * 64 + mt * 16 + g + hh * 8;
                    size_t off = (size_t)(bm + row_l) * DD + bn + col_l;
                    float2 iv = *reinterpret_cast<const float2*>(inputs + off);
                    float2 e = *reinterpret_cast<const float2*>(ex + row_l * EXP + col_l);
                    float2 o;
                    o.x = sigf(c[hh * 2 + 0] + bb.x) * iv.x + e.x;
                    o.y = sigf(c[hh * 2 + 1] + bb.y) * iv.y + e.y;
                    *reinterpret_cast<float2*>(out + off) = o;
                }
            }
        }
    }
#undef G3_LOAD
}

// ---------------- launch -----------------------------------------------------
extern "C" void kernel_launch(void* const* d_in, const int* in_sizes, int n_in,
                              void* d_out, int out_size) {
    const float* inputs = (const float*)d_in[0];
    const float* w1 = (const float*)d_in[1];
    const float* b1 = (const float*)d_in[2];
    const float* w2 = (const float*)d_in[3];
    const float* b2 = (const float*)d_in[4];
    const float* lng = (const float*)d_in[5];
    const float* lnb = (const float*)d_in[6];
    const float* wg = (const float*)d_in[7];
    const float* bg = (const float*)d_in[8];
    float* out = (float*)d_out;

    float *avg, *h, *inter, *avgout, *avgout_r, *in_r, *w1t, *w2t, *wgt;
    cudaGetSymbolAddress((void**)&avg, g_avg);
    cudaGetSymbolAddress((void**)&h, g_h);
    cudaGetSymbolAddress((void**)&inter, g_inter);
    cudaGetSymbolAddress((void**)&avgout, g_avgout);
    cudaGetSymbolAddress((void**)&avgout_r, g_avgout_r);
    cudaGetSymbolAddress((void**)&in_r, g_in_r);
    cudaGetSymbolAddress((void**)&w1t, g_w1t);
    cudaGetSymbolAddress((void**)&w2t, g_w2t);
    cudaGetSymbolAddress((void**)&wgt, g_wgt);

    cudaFuncSetAttribute(k_gemm_mma<0, DD, DD>,
                         cudaFuncAttributeMaxDynamicSharedMemorySize, GEMM_SMEM);
    cudaFuncSetAttribute(k_gemm_mma<1, DD, DD>,
                         cudaFuncAttributeMaxDynamicSharedMemorySize, GEMM_SMEM);
    cudaFuncSetAttribute(k_gemm3_fused,
                         cudaFuncAttributeMaxDynamicSharedMemorySize, G3_SMEM);

    dim3 tb(32, 8);
    k_transpose<<<dim3(DD / 32, DD / 32), tb>>>(w1, w1t, DD);
    k_transpose<<<dim3(DD / 32, DD / 32), tb>>>(w2, w2t, DD);
    k_transpose<<<dim3(DD2 / 32, DD2 / 32), tb>>>(wg, wgt, DD2);

    k_chunksum<<<(BB * NCH * DD) / 256, 256>>>(inputs);
    k_scan<<<(BB * DD) / 256, 256>>>();
    k_apply<<<(BB * NCH * DD) / 256, 256>>>(inputs);
    k_ln<<<MM, 256>>>(lng, lnb);

    dim3 grid12(DD / 128, MM / 128);     // (8, 256)
    k_gemm_mma<0, DD, DD><<<grid12, 256, GEMM_SMEM>>>(h, w1t, b1, nullptr,
                                                      inter, nullptr);
    k_gemm_mma<1, DD, DD><<<grid12, 256, GEMM_SMEM>>>(inter, w2t, b2, avg,
                                                      avgout, avgout_r);

    dim3 grid3(DD / 128, MM / 128);      // (8, 256)
    k_gemm3_fused<<<grid3, 512, G3_SMEM>>>(in_r, avgout_r, wgt, bg,
                                           inputs, avgout, out);
}

// round 6
// speedup vs baseline: 1.9976x; 1.9976x over previous
#include <cuda_runtime.h>
#include <cuda_fp16.h>
#include <math.h>
#include <stdint.h>

#define BB 8
#define LL 4096
#define DD 1024
#define MM (BB * LL)          // 32768 rows
#define DD2 (2 * DD)          // 2048
#define NCH 32
#define CHUNK (LL / NCH)      // 128

// ---------------- scratch (device globals; no allocation allowed) ----------
__device__ float  g_avg[(size_t)MM * DD];      // cumulative mean (fp32)
__device__ float  g_avgout[(size_t)MM * DD];   // inter@w2+b2+avg (fp32)
__device__ __half g_h_h[(size_t)MM * DD];      // layernorm(avg), fp16
__device__ __half g_inter_h[(size_t)MM * DD];  // relu(h@w1+b1), fp16
__device__ __half g_avgout_h[(size_t)MM * DD]; // fp16 copy of avgout
__device__ __half g_in_h[(size_t)MM * DD];     // fp16 inputs
__device__ __half g_gates_h[(size_t)MM * DD2]; // concat@wg+bg, fp16
__device__ float  g_csum[BB * NCH * DD];       // chunk partial sums
__device__ __half g_w1t[DD * DD];              // w1^T [N][K], fp16
__device__ __half g_w2t[DD * DD];
__device__ __half g_wgt[(size_t)DD2 * DD2];

// ---------------- helpers ----------------------------------------------------
__device__ __forceinline__ float sigf(float x) { return 1.f / (1.f + expf(-x)); }

#define CP_ASYNC16(dst, src) \
    asm volatile("cp.async.cg.shared.global [%0], [%1], 16;" \
                 :: "r"(dst), "l"(src) : "memory")
#define CP_COMMIT() asm volatile("cp.async.commit_group;" ::: "memory")

#define MMA_F16(c, a0, a1, a2, a3, b0, b1)                                    \
    asm volatile(                                                             \
        "mma.sync.aligned.m16n8k16.row.col.f32.f16.f16.f32 "                  \
        "{%0,%1,%2,%3}, {%4,%5,%6,%7}, {%8,%9}, {%0,%1,%2,%3};"               \
        : "+f"((c)[0]), "+f"((c)[1]), "+f"((c)[2]), "+f"((c)[3])              \
        : "r"(a0), "r"(a1), "r"(a2), "r"(a3), "r"(b0), "r"(b1))

// ---------------- phase 1: chunked cumulative sum --------------------------
__global__ void __launch_bounds__(256) k_chunksum(const float* __restrict__ in) {
    int idx = blockIdx.x * blockDim.x + threadIdx.x;
    int d = idx & (DD - 1);
    int chunk = (idx >> 10) & (NCH - 1);
    int b = idx >> 15;
    const float* p = in + ((size_t)(b * LL + chunk * CHUNK)) * DD + d;
    float s = 0.f;
#pragma unroll 4
    for (int l = 0; l < CHUNK; ++l) s += p[(size_t)l * DD];
    g_csum[(b * NCH + chunk) * DD + d] = s;
}

__global__ void __launch_bounds__(256) k_scan() {
    int idx = blockIdx.x * blockDim.x + threadIdx.x;
    int d = idx & (DD - 1);
    int b = idx >> 10;
    float run = 0.f;
#pragma unroll
    for (int c = 0; c < NCH; ++c) {
        int o = (b * NCH + c) * DD + d;
        float t = g_csum[o];
        g_csum[o] = run;
        run += t;
    }
}

__global__ void __launch_bounds__(256) k_apply(const float* __restrict__ in) {
    int idx = blockIdx.x * blockDim.x + threadIdx.x;
    int d = idx & (DD - 1);
    int chunk = (idx >> 10) & (NCH - 1);
    int b = idx >> 15;
    size_t base = ((size_t)(b * LL + chunk * CHUNK)) * DD + d;
    const float* p = in + base;
    float* q = g_avg + base;
    __half* qh = g_in_h + base;
    float run = g_csum[(b * NCH + chunk) * DD + d];
    int l0 = chunk * CHUNK;
#pragma unroll 4
    for (int l = 0; l < CHUNK; ++l) {
        float v = p[(size_t)l * DD];
        run += v;
        q[(size_t)l * DD] = run / (float)(l0 + l + 1);
        qh[(size_t)l * DD] = __float2half_rn(v);
    }
}

// ---------------- phase 2: layernorm over D per row (fp16 out) ---------------
__global__ void __launch_bounds__(256) k_ln(const float* __restrict__ lng,
                                            const float* __restrict__ lnb) {
    int row = blockIdx.x;
    int t = threadIdx.x;
    const float4* x4 = reinterpret_cast<const float4*>(g_avg + (size_t)row * DD);
    float4 a = x4[t];
    float s = a.x + a.y + a.z + a.w;
    float ss = a.x * a.x + a.y * a.y + a.z * a.z + a.w * a.w;
#pragma unroll
    for (int o = 16; o > 0; o >>= 1) {
        s  += __shfl_xor_sync(0xffffffffu, s, o);
        ss += __shfl_xor_sync(0xffffffffu, ss, o);
    }
    __shared__ float sm[16];
    int w = t >> 5;
    if ((t & 31) == 0) { sm[w] = s; sm[8 + w] = ss; }
    __syncthreads();
    if (t < 32) {
        float v1 = (t < 8) ? sm[t] : 0.f;
        float v2 = (t < 8) ? sm[8 + t] : 0.f;
#pragma unroll
        for (int o = 4; o > 0; o >>= 1) {
            v1 += __shfl_xor_sync(0xffffffffu, v1, o);
            v2 += __shfl_xor_sync(0xffffffffu, v2, o);
        }
        if (t == 0) { sm[0] = v1; sm[1] = v2; }
    }
    __syncthreads();
    float mean = sm[0] * (1.f / DD);
    float var  = sm[1] * (1.f / DD) - mean * mean;
    float inv  = rsqrtf(var + 1e-6f);
    float4 g = reinterpret_cast<const float4*>(lng)[t];
    float4 b = reinterpret_cast<const float4*>(lnb)[t];
    __half2 h0 = __floats2half2_rn((a.x - mean) * inv * g.x + b.x,
                                   (a.y - mean) * inv * g.y + b.y);
    __half2 h1 = __floats2half2_rn((a.z - mean) * inv * g.z + b.z,
                                   (a.w - mean) * inv * g.w + b.w);
    __half2* dst = reinterpret_cast<__half2*>(g_h_h + (size_t)row * DD);
    dst[t * 2 + 0] = h0;
    dst[t * 2 + 1] = h1;
}

// ---------------- weight transpose (fp16 out): Wt[n][k] = W[k][n] ------------
__global__ void __launch_bounds__(256) k_transpose(const float* __restrict__ W,
                                                   __half* __restrict__ Wt, int N) {
    __shared__ float t[32][33];
    int bx = blockIdx.x * 32, by = blockIdx.y * 32;
    int x = bx + threadIdx.x;
#pragma unroll
    for (int i = 0; i < 32; i += 8)
        t[threadIdx.y + i][threadIdx.x] = W[(size_t)(by + threadIdx.y + i) * N + x];
    __syncthreads();
    int x2 = by + threadIdx.x;
#pragma unroll
    for (int i = 0; i < 32; i += 8)
        Wt[(size_t)(bx + threadIdx.y + i) * N + x2] =
            __float2half_rn(t[threadIdx.x][threadIdx.y + i]);
}

// ---------------- phase 3: fp16 mma.sync GEMM --------------------------------
// C[M,NN] = concatA[M,KTOT] @ Wt[NN,KTOT]^T (fp16 operands, fp32 accum).
// CTA tile 128x128, BK=64 halves, 8 warps (2x4), warp tile 64x32, m16n8k16.
// Smem pitch 72 halves: conflict-free 4B fragment loads, 16B cp.async.
// MODE 0: relu(x+b) -> Ch (inter)
// MODE 1: x+b+add -> Cf (avgout) and fp16 copy -> Ch
// MODE 2: x+b -> Ch (gates)
#define LDPH 72
#define TILE_H (128 * LDPH)               // halves per tile
#define STG_H (2 * TILE_H)                // A + B per stage
#define GEMM_SMEM (2 * STG_H * 2)         // 2 stages = 73728 B

template <int MODE, int KTOT, int NN>
__global__ void __launch_bounds__(256, 2) k_gemm_h(
    const __half* __restrict__ A0, const __half* __restrict__ A1,
    const __half* __restrict__ Wt, const float* __restrict__ bias,
    const float* __restrict__ add, float* __restrict__ Cf,
    __half* __restrict__ Ch) {
    extern __shared__ __half smh[];
    int tid = threadIdx.x;
    int wid = tid >> 5, lane = tid & 31;
    int g = lane >> 2, tg = lane & 3;
    int wm = wid >> 2, wn = wid & 3;       // 2 x 4 warp grid
    int bm = blockIdx.y * 128, bn = blockIdx.x * 128;

    float acc[16][4];
#pragma unroll
    for (int i = 0; i < 16; ++i)
#pragma unroll
        for (int j = 0; j < 4; ++j) acc[i][j] = 0.f;

    const int NK = KTOT / 64;

#define LOAD_STAGE(s, kk_)                                                     \
    {                                                                          \
        int kk = (kk_);                                                        \
        const __half* Ab = A0; int kloc = kk;                                  \
        if (KTOT > DD && kk >= DD) { Ab = A1; kloc = kk - DD; }                \
        __half* As = smh + (s) * STG_H;                                        \
        __half* Bs = As + TILE_H;                                              \
        _Pragma("unroll")                                                      \
        for (int it = 0; it < 4; ++it) {                                       \
            int i = tid + it * 256;                                            \
            int r = i >> 3, c = (i & 7) << 3;                                  \
            uint32_t da = (uint32_t)__cvta_generic_to_shared(As + r * LDPH + c); \
            CP_ASYNC16(da, Ab + (size_t)(bm + r) * DD + kloc + c);             \
            uint32_t db = (uint32_t)__cvta_generic_to_shared(Bs + r * LDPH + c); \
            CP_ASYNC16(db, Wt + (size_t)(bn + r) * KTOT + kk + c);             \
        }                                                                      \
    }

    LOAD_STAGE(0, 0);
    CP_COMMIT();

    for (int kt = 0; kt < NK; ++kt) {
        int cur = kt & 1;
        if (kt + 1 < NK) {
            LOAD_STAGE(cur ^ 1, (kt + 1) * 64);
            CP_COMMIT();
            asm volatile("cp.async.wait_group 1;" ::: "memory");
        } else {
            asm volatile("cp.async.wait_group 0;" ::: "memory");
        }
        __syncthreads();

        const __half* As = smh + cur * STG_H;
        const __half* Bs = As + TILE_H;
#pragma unroll
        for (int kc = 0; kc < 4; ++kc) {
            int kb = kc * 16;
            uint32_t af[4][4], bf[4][2];
#pragma unroll
            for (int mt = 0; mt < 4; ++mt) {
                int r0 = (wm * 64 + mt * 16 + g) * LDPH + kb + 2 * tg;
                af[mt][0] = *reinterpret_cast<const uint32_t*>(As + r0);
                af[mt][1] = *reinterpret_cast<const uint32_t*>(As + r0 + 8 * LDPH);
                af[mt][2] = *reinterpret_cast<const uint32_t*>(As + r0 + 8);
                af[mt][3] = *reinterpret_cast<const uint32_t*>(As + r0 + 8 * LDPH + 8);
            }
#pragma unroll
            for (int nt = 0; nt < 4; ++nt) {
                int r0 = (wn * 32 + nt * 8 + g) * LDPH + kb + 2 * tg;
                bf[nt][0] = *reinterpret_cast<const uint32_t*>(Bs + r0);
                bf[nt][1] = *reinterpret_cast<const uint32_t*>(Bs + r0 + 8);
            }
#pragma unroll
            for (int mt = 0; mt < 4; ++mt)
#pragma unroll
                for (int nt = 0; nt < 4; ++nt)
                    MMA_F16(acc[mt * 4 + nt], af[mt][0], af[mt][1], af[mt][2],
                            af[mt][3], bf[nt][0], bf[nt][1]);
        }
        __syncthreads();
    }

#pragma unroll
    for (int mt = 0; mt < 4; ++mt) {
#pragma unroll
        for (int nt = 0; nt < 4; ++nt) {
            float* c = acc[mt * 4 + nt];
            int col = bn + wn * 32 + nt * 8 + 2 * tg;
            float2 bb = *reinterpret_cast<const float2*>(bias + col);
#pragma unroll
            for (int hh = 0; hh < 2; ++hh) {
                int row = bm + wm * 64 + mt * 16 + g + hh * 8;
                size_t off = (size_t)row * NN + col;
                float vx = c[hh * 2 + 0] + bb.x;
                float vy = c[hh * 2 + 1] + bb.y;
                if (MODE == 0) {
                    *reinterpret_cast<__half2*>(Ch + off) =
                        __floats2half2_rn(fmaxf(vx, 0.f), fmaxf(vy, 0.f));
                } else if (MODE == 1) {
                    float2 ad = *reinterpret_cast<const float2*>(add + off);
                    vx += ad.x; vy += ad.y;
                    float2 o; o.x = vx; o.y = vy;
                    *reinterpret_cast<float2*>(Cf + off) = o;
                    *reinterpret_cast<__half2*>(Ch + off) = __floats2half2_rn(vx, vy);
                } else {
                    *reinterpret_cast<__half2*>(Ch + off) = __floats2half2_rn(vx, vy);
                }
            }
        }
    }
#undef LOAD_STAGE
}

// ---------------- phase 4: gate combine --------------------------------------
__global__ void __launch_bounds__(256) k_final(const float* __restrict__ in,
                                               float* __restrict__ out) {
    int idx = blockIdx.x * blockDim.x + threadIdx.x;   // over M*D/4
    int row = idx >> 8;                                 // D/4 = 256
    int d4 = idx & 255;
    float4 i4 = reinterpret_cast<const float4*>(in)[idx];
    float4 a4 = reinterpret_cast<const float4*>(g_avgout)[idx];
    const __half2* gr = reinterpret_cast<const __half2*>(
        g_gates_h + (size_t)row * DD2);
    __half2 g1a = gr[d4 * 2 + 0];
    __half2 g1b = gr[d4 * 2 + 1];
    __half2 g2a = gr[512 + d4 * 2 + 0];
    __half2 g2b = gr[512 + d4 * 2 + 1];
    float4 o;
    o.x = sigf(__low2float(g1a))  * i4.x + sigf(__low2float(g2a))  * a4.x;
    o.y = sigf(__high2float(g1a)) * i4.y + sigf(__high2float(g2a)) * a4.y;
    o.z = sigf(__low2float(g1b))  * i4.z + sigf(__low2float(g2b))  * a4.z;
    o.w = sigf(__high2float(g1b)) * i4.w + sigf(__high2float(g2b)) * a4.w;
    reinterpret_cast<float4*>(out)[idx] = o;
}

// ---------------- launch -----------------------------------------------------
extern "C" void kernel_launch(void* const* d_in, const int* in_sizes, int n_in,
                              void* d_out, int out_size) {
    const float* inputs = (const float*)d_in[0];
    const float* w1 = (const float*)d_in[1];
    const float* b1 = (const float*)d_in[2];
    const float* w2 = (const float*)d_in[3];
    const float* b2 = (const float*)d_in[4];
    const float* lng = (const float*)d_in[5];
    const float* lnb = (const float*)d_in[6];
    const float* wg = (const float*)d_in[7];
    const float* bg = (const float*)d_in[8];
    float* out = (float*)d_out;

    float *avg, *avgout;
    __half *hh, *interh, *avgouth, *inh, *gatesh, *w1t, *w2t, *wgt;
    cudaGetSymbolAddress((void**)&avg, g_avg);
    cudaGetSymbolAddress((void**)&avgout, g_avgout);
    cudaGetSymbolAddress((void**)&hh, g_h_h);
    cudaGetSymbolAddress((void**)&interh, g_inter_h);
    cudaGetSymbolAddress((void**)&avgouth, g_avgout_h);
    cudaGetSymbolAddress((void**)&inh, g_in_h);
    cudaGetSymbolAddress((void**)&gatesh, g_gates_h);
    cudaGetSymbolAddress((void**)&w1t, g_w1t);
    cudaGetSymbolAddress((void**)&w2t, g_w2t);
    cudaGetSymbolAddress((void**)&wgt, g_wgt);

    cudaFuncSetAttribute(k_gemm_h<0, DD, DD>,
                         cudaFuncAttributeMaxDynamicSharedMemorySize, GEMM_SMEM);
    cudaFuncSetAttribute(k_gemm_h<1, DD, DD>,
                         cudaFuncAttributeMaxDynamicSharedMemorySize, GEMM_SMEM);
    cudaFuncSetAttribute(k_gemm_h<2, DD2, DD2>,
                         cudaFuncAttributeMaxDynamicSharedMemorySize, GEMM_SMEM);

    dim3 tb(32, 8);
    k_transpose<<<dim3(DD / 32, DD / 32), tb>>>(w1, w1t, DD);
    k_transpose<<<dim3(DD / 32, DD / 32), tb>>>(w2, w2t, DD);
    k_transpose<<<dim3(DD2 / 32, DD2 / 32), tb>>>(wg, wgt, DD2);

    k_chunksum<<<(BB * NCH * DD) / 256, 256>>>(inputs);
    k_scan<<<(BB * DD) / 256, 256>>>();
    k_apply<<<(BB * NCH * DD) / 256, 256>>>(inputs);
    k_ln<<<MM, 256>>>(lng, lnb);

    dim3 grid12(DD / 128, MM / 128);     // (8, 256)
    k_gemm_h<0, DD, DD><<<grid12, 256, GEMM_SMEM>>>(hh, hh, w1t, b1, nullptr,
                                                    nullptr, interh);
    k_gemm_h<1, DD, DD><<<grid12, 256, GEMM_SMEM>>>(interh, interh, w2t, b2, avg,
                                                    avgout, avgouth);

    dim3 grid3(DD2 / 128, MM / 128);     // (16, 256)
    k_gemm_h<2, DD2, DD2><<<grid3, 256, GEMM_SMEM>>>(inh, avgouth, wgt, bg,
                                                     nullptr, nullptr, gatesh);

    k_final<<<((size_t)MM * DD / 4) / 256, 256>>>(inputs, out);
}

// round 7
// speedup vs baseline: 2.1658x; 1.0842x over previous
#include <cuda_runtime.h>
#include <cuda_fp16.h>
#include <math.h>
#include <stdint.h>

#define BB 8
#define LL 4096
#define DD 1024
#define MM (BB * LL)          // 32768 rows
#define DD2 (2 * DD)          // 2048
#define NCH 32
#define CHUNK (LL / NCH)      // 128

// ---------------- scratch (device globals; no allocation allowed) ----------
__device__ float  g_avg[(size_t)MM * DD];      // cumulative mean (fp32)
__device__ float  g_avgout[(size_t)MM * DD];   // inter@w2+b2+avg (fp32)
__device__ __half g_h_h[(size_t)MM * DD];      // layernorm(avg), fp16
__device__ __half g_inter_h[(size_t)MM * DD];  // relu(h@w1+b1), fp16
__device__ __half g_avgout_h[(size_t)MM * DD]; // fp16 copy of avgout
__device__ __half g_in_h[(size_t)MM * DD];     // fp16 inputs
__device__ __half g_gates_h[(size_t)MM * DD2]; // concat@wg+bg, fp16
__device__ float  g_csum[BB * NCH * DD];       // chunk partial sums
__device__ __half g_w1t[DD * DD];              // w1^T [N][K], fp16
__device__ __half g_w2t[DD * DD];
__device__ __half g_wgt[(size_t)DD2 * DD2];

// ---------------- helpers ----------------------------------------------------
__device__ __forceinline__ float sigf(float x) { return 1.f / (1.f + expf(-x)); }

#define CP_ASYNC16(dst, src) \
    asm volatile("cp.async.cg.shared.global [%0], [%1], 16;" \
                 :: "r"(dst), "l"(src) : "memory")
#define CP_COMMIT() asm volatile("cp.async.commit_group;" ::: "memory")

#define MMA_F16(c, a0, a1, a2, a3, b0, b1)                                    \
    asm volatile(                                                             \
        "mma.sync.aligned.m16n8k16.row.col.f32.f16.f16.f32 "                  \
        "{%0,%1,%2,%3}, {%4,%5,%6,%7}, {%8,%9}, {%0,%1,%2,%3};"               \
        : "+f"((c)[0]), "+f"((c)[1]), "+f"((c)[2]), "+f"((c)[3])              \
        : "r"(a0), "r"(a1), "r"(a2), "r"(a3), "r"(b0), "r"(b1))

#define LDSM_X4(r0, r1, r2, r3, addr)                                         \
    asm volatile("ldmatrix.sync.aligned.m8n8.x4.shared.b16 {%0,%1,%2,%3}, [%4];" \
                 : "=r"(r0), "=r"(r1), "=r"(r2), "=r"(r3) : "r"(addr))

// ---------------- phase 1: chunked cumulative sum --------------------------
__global__ void __launch_bounds__(256) k_chunksum(const float* __restrict__ in) {
    int idx = blockIdx.x * blockDim.x + threadIdx.x;
    int d = idx & (DD - 1);
    int chunk = (idx >> 10) & (NCH - 1);
    int b = idx >> 15;
    const float* p = in + ((size_t)(b * LL + chunk * CHUNK)) * DD + d;
    float s = 0.f;
#pragma unroll 4
    for (int l = 0; l < CHUNK; ++l) s += p[(size_t)l * DD];
    g_csum[(b * NCH + chunk) * DD + d] = s;
}

__global__ void __launch_bounds__(256) k_scan() {
    int idx = blockIdx.x * blockDim.x + threadIdx.x;
    int d = idx & (DD - 1);
    int b = idx >> 10;
    float run = 0.f;
#pragma unroll
    for (int c = 0; c < NCH; ++c) {
        int o = (b * NCH + c) * DD + d;
        float t = g_csum[o];
        g_csum[o] = run;
        run += t;
    }
}

__global__ void __launch_bounds__(256) k_apply(const float* __restrict__ in) {
    int idx = blockIdx.x * blockDim.x + threadIdx.x;
    int d = idx & (DD - 1);
    int chunk = (idx >> 10) & (NCH - 1);
    int b = idx >> 15;
    size_t base = ((size_t)(b * LL + chunk * CHUNK)) * DD + d;
    const float* p = in + base;
    float* q = g_avg + base;
    __half* qh = g_in_h + base;
    float run = g_csum[(b * NCH + chunk) * DD + d];
    int l0 = chunk * CHUNK;
#pragma unroll 4
    for (int l = 0; l < CHUNK; ++l) {
        float v = p[(size_t)l * DD];
        run += v;
        q[(size_t)l * DD] = run / (float)(l0 + l + 1);
        qh[(size_t)l * DD] = __float2half_rn(v);
    }
}

// ---------------- phase 2: layernorm over D per row (fp16 out) ---------------
__global__ void __launch_bounds__(256) k_ln(const float* __restrict__ lng,
                                            const float* __restrict__ lnb) {
    int row = blockIdx.x;
    int t = threadIdx.x;
    const float4* x4 = reinterpret_cast<const float4*>(g_avg + (size_t)row * DD);
    float4 a = x4[t];
    float s = a.x + a.y + a.z + a.w;
    float ss = a.x * a.x + a.y * a.y + a.z * a.z + a.w * a.w;
#pragma unroll
    for (int o = 16; o > 0; o >>= 1) {
        s  += __shfl_xor_sync(0xffffffffu, s, o);
        ss += __shfl_xor_sync(0xffffffffu, ss, o);
    }
    __shared__ float sm[16];
    int w = t >> 5;
    if ((t & 31) == 0) { sm[w] = s; sm[8 + w] = ss; }
    __syncthreads();
    if (t < 32) {
        float v1 = (t < 8) ? sm[t] : 0.f;
        float v2 = (t < 8) ? sm[8 + t] : 0.f;
#pragma unroll
        for (int o = 4; o > 0; o >>= 1) {
            v1 += __shfl_xor_sync(0xffffffffu, v1, o);
            v2 += __shfl_xor_sync(0xffffffffu, v2, o);
        }
        if (t == 0) { sm[0] = v1; sm[1] = v2; }
    }
    __syncthreads();
    float mean = sm[0] * (1.f / DD);
    float var  = sm[1] * (1.f / DD) - mean * mean;
    float inv  = rsqrtf(var + 1e-6f);
    float4 g = reinterpret_cast<const float4*>(lng)[t];
    float4 b = reinterpret_cast<const float4*>(lnb)[t];
    __half2 h0 = __floats2half2_rn((a.x - mean) * inv * g.x + b.x,
                                   (a.y - mean) * inv * g.y + b.y);
    __half2 h1 = __floats2half2_rn((a.z - mean) * inv * g.z + b.z,
                                   (a.w - mean) * inv * g.w + b.w);
    __half2* dst = reinterpret_cast<__half2*>(g_h_h + (size_t)row * DD);
    dst[t * 2 + 0] = h0;
    dst[t * 2 + 1] = h1;
}

// ---------------- weight transpose (fp16 out): Wt[n][k] = W[k][n] ------------
__global__ void __launch_bounds__(256) k_transpose(const float* __restrict__ W,
                                                   __half* __restrict__ Wt, int N) {
    __shared__ float t[32][33];
    int bx = blockIdx.x * 32, by = blockIdx.y * 32;
    int x = bx + threadIdx.x;
#pragma unroll
    for (int i = 0; i < 32; i += 8)
        t[threadIdx.y + i][threadIdx.x] = W[(size_t)(by + threadIdx.y + i) * N + x];
    __syncthreads();
    int x2 = by + threadIdx.x;
#pragma unroll
    for (int i = 0; i < 32; i += 8)
        Wt[(size_t)(bx + threadIdx.y + i) * N + x2] =
            __float2half_rn(t[threadIdx.x][threadIdx.y + i]);
}

// ---------------- phase 3: fp16 mma.sync GEMM (ldmatrix fragments) -----------
// C[M,NN] = concatA[M,KTOT] @ Wt[NN,KTOT]^T (fp16 operands, fp32 accum).
// CTA tile 128x128, BK=64 halves, 8 warps (2x4), warp tile 64x32, m16n8k16.
// Fragments via ldmatrix.x4 (6 LDSM/warp/k16 vs 24 LDS.32).
// MODE 0: relu(x+b) -> Ch   MODE 1: x+b+add -> Cf + fp16 Ch   MODE 2: x+b -> Ch
#define LDPH 72
#define TILE_H (128 * LDPH)               // halves per tile
#define STG_H (2 * TILE_H)                // A + B per stage
#define GEMM_SMEM (2 * STG_H * 2)         // 2 stages = 73728 B

template <int MODE, int KTOT, int NN>
__global__ void __launch_bounds__(256, 2) k_gemm_h(
    const __half* __restrict__ A0, const __half* __restrict__ A1,
    const __half* __restrict__ Wt, const float* __restrict__ bias,
    const float* __restrict__ add, float* __restrict__ Cf,
    __half* __restrict__ Ch) {
    extern __shared__ __half smh[];
    int tid = threadIdx.x;
    int wid = tid >> 5, lane = tid & 31;
    int g = lane >> 2, tg = lane & 3;
    int wm = wid >> 2, wn = wid & 3;       // 2 x 4 warp grid
    int bm = blockIdx.y * 128, bn = blockIdx.x * 128;

    // per-lane ldmatrix offsets (in halves, within tile)
    int la_off = (lane & 15) * LDPH + (lane >> 4) * 8;                 // A x4
    int qb = lane >> 3;
    int lb_off = ((lane & 7) + (qb >> 1) * 8) * LDPH + (qb & 1) * 8;   // B x4

    float acc[16][4];
#pragma unroll
    for (int i = 0; i < 16; ++i)
#pragma unroll
        for (int j = 0; j < 4; ++j) acc[i][j] = 0.f;

    const int NK = KTOT / 64;

#define LOAD_STAGE(s, kk_)                                                     \
    {                                                                          \
        int kk = (kk_);                                                        \
        const __half* Ab = A0; int kloc = kk;                                  \
        if (KTOT > DD && kk >= DD) { Ab = A1; kloc = kk - DD; }                \
        __half* As = smh + (s) * STG_H;                                        \
        __half* Bs = As + TILE_H;                                              \
        _Pragma("unroll")                                                      \
        for (int it = 0; it < 4; ++it) {                                       \
            int i = tid + it * 256;                                            \
            int r = i >> 3, c = (i & 7) << 3;                                  \
            uint32_t da = (uint32_t)__cvta_generic_to_shared(As + r * LDPH + c); \
            CP_ASYNC16(da, Ab + (size_t)(bm + r) * DD + kloc + c);             \
            uint32_t db = (uint32_t)__cvta_generic_to_shared(Bs + r * LDPH + c); \
            CP_ASYNC16(db, Wt + (size_t)(bn + r) * KTOT + kk + c);             \
        }                                                                      \
    }

    LOAD_STAGE(0, 0);
    CP_COMMIT();

    for (int kt = 0; kt < NK; ++kt) {
        int cur = kt & 1;
        if (kt + 1 < NK) {
            LOAD_STAGE(cur ^ 1, (kt + 1) * 64);
            CP_COMMIT();
            asm volatile("cp.async.wait_group 1;" ::: "memory");
        } else {
            asm volatile("cp.async.wait_group 0;" ::: "memory");
        }
        __syncthreads();

        const __half* As = smh + cur * STG_H;
        const __half* Bs = As + TILE_H;
        uint32_t aB = (uint32_t)__cvta_generic_to_shared(
            As + (size_t)(wm * 64) * LDPH + la_off);
        uint32_t bB = (uint32_t)__cvta_generic_to_shared(
            Bs + (size_t)(wn * 32) * LDPH + lb_off);
#pragma unroll
        for (int kc = 0; kc < 4; ++kc) {
            int kb2 = kc * 32;                       // byte offset of k16 chunk
            uint32_t af[4][4], bf[4][2];
#pragma unroll
            for (int mt = 0; mt < 4; ++mt)
                LDSM_X4(af[mt][0], af[mt][1], af[mt][2], af[mt][3],
                        aB + mt * (16 * LDPH * 2) + kb2);
#pragma unroll
            for (int p = 0; p < 2; ++p)
                LDSM_X4(bf[p * 2][0], bf[p * 2][1], bf[p * 2 + 1][0],
                        bf[p * 2 + 1][1], bB + p * (16 * LDPH * 2) + kb2);
#pragma unroll
            for (int mt = 0; mt < 4; ++mt)
#pragma unroll
                for (int nt = 0; nt < 4; ++nt)
                    MMA_F16(acc[mt * 4 + nt], af[mt][0], af[mt][1], af[mt][2],
                            af[mt][3], bf[nt][0], bf[nt][1]);
        }
        __syncthreads();
    }

#pragma unroll
    for (int mt = 0; mt < 4; ++mt) {
#pragma unroll
        for (int nt = 0; nt < 4; ++nt) {
            float* c = acc[mt * 4 + nt];
            int col = bn + wn * 32 + nt * 8 + 2 * tg;
            float2 bb = *reinterpret_cast<const float2*>(bias + col);
#pragma unroll
            for (int hh = 0; hh < 2; ++hh) {
                int row = bm + wm * 64 + mt * 16 + g + hh * 8;
                size_t off = (size_t)row * NN + col;
                float vx = c[hh * 2 + 0] + bb.x;
                float vy = c[hh * 2 + 1] + bb.y;
                if (MODE == 0) {
                    *reinterpret_cast<__half2*>(Ch + off) =
                        __floats2half2_rn(fmaxf(vx, 0.f), fmaxf(vy, 0.f));
                } else if (MODE == 1) {
                    float2 ad = *reinterpret_cast<const float2*>(add + off);
                    vx += ad.x; vy += ad.y;
                    float2 o; o.x = vx; o.y = vy;
                    *reinterpret_cast<float2*>(Cf + off) = o;
                    *reinterpret_cast<__half2*>(Ch + off) = __floats2half2_rn(vx, vy);
                } else {
                    *reinterpret_cast<__half2*>(Ch + off) = __floats2half2_rn(vx, vy);
                }
            }
        }
    }
#undef LOAD_STAGE
}

// ---------------- phase 4: gate combine --------------------------------------
__global__ void __launch_bounds__(256) k_final(const float* __restrict__ in,
                                               float* __restrict__ out) {
    int idx = blockIdx.x * blockDim.x + threadIdx.x;   // over M*D/4
    int row = idx >> 8;                                 // D/4 = 256
    int d4 = idx & 255;
    float4 i4 = reinterpret_cast<const float4*>(in)[idx];
    float4 a4 = reinterpret_cast<const float4*>(g_avgout)[idx];
    const __half2* gr = reinterpret_cast<const __half2*>(
        g_gates_h + (size_t)row * DD2);
    __half2 g1a = gr[d4 * 2 + 0];
    __half2 g1b = gr[d4 * 2 + 1];
    __half2 g2a = gr[512 + d4 * 2 + 0];
    __half2 g2b = gr[512 + d4 * 2 + 1];
    float4 o;
    o.x = sigf(__low2float(g1a))  * i4.x + sigf(__low2float(g2a))  * a4.x;
    o.y = sigf(__high2float(g1a)) * i4.y + sigf(__high2float(g2a)) * a4.y;
    o.z = sigf(__low2float(g1b))  * i4.z + sigf(__low2float(g2b))  * a4.z;
    o.w = sigf(__high2float(g1b)) * i4.w + sigf(__high2float(g2b)) * a4.w;
    reinterpret_cast<float4*>(out)[idx] = o;
}

// ---------------- launch -----------------------------------------------------
extern "C" void kernel_launch(void* const* d_in, const int* in_sizes, int n_in,
                              void* d_out, int out_size) {
    const float* inputs = (const float*)d_in[0];
    const float* w1 = (const float*)d_in[1];
    const float* b1 = (const float*)d_in[2];
    const float* w2 = (const float*)d_in[3];
    const float* b2 = (const float*)d_in[4];
    const float* lng = (const float*)d_in[5];
    const float* lnb = (const float*)d_in[6];
    const float* wg = (const float*)d_in[7];
    const float* bg = (const float*)d_in[8];
    float* out = (float*)d_out;

    float *avg, *avgout;
    __half *hh, *interh, *avgouth, *inh, *gatesh, *w1t, *w2t, *wgt;
    cudaGetSymbolAddress((void**)&avg, g_avg);
    cudaGetSymbolAddress((void**)&avgout, g_avgout);
    cudaGetSymbolAddress((void**)&hh, g_h_h);
    cudaGetSymbolAddress((void**)&interh, g_inter_h);
    cudaGetSymbolAddress((void**)&avgouth, g_avgout_h);
    cudaGetSymbolAddress((void**)&inh, g_in_h);
    cudaGetSymbolAddress((void**)&gatesh, g_gates_h);
    cudaGetSymbolAddress((void**)&w1t, g_w1t);
    cudaGetSymbolAddress((void**)&w2t, g_w2t);
    cudaGetSymbolAddress((void**)&wgt, g_wgt);

    cudaFuncSetAttribute(k_gemm_h<0, DD, DD>,
                         cudaFuncAttributeMaxDynamicSharedMemorySize, GEMM_SMEM);
    cudaFuncSetAttribute(k_gemm_h<1, DD, DD>,
                         cudaFuncAttributeMaxDynamicSharedMemorySize, GEMM_SMEM);
    cudaFuncSetAttribute(k_gemm_h<2, DD2, DD2>,
                         cudaFuncAttributeMaxDynamicSharedMemorySize, GEMM_SMEM);

    dim3 tb(32, 8);
    k_transpose<<<dim3(DD / 32, DD / 32), tb>>>(w1, w1t, DD);
    k_transpose<<<dim3(DD / 32, DD / 32), tb>>>(w2, w2t, DD);
    k_transpose<<<dim3(DD2 / 32, DD2 / 32), tb>>>(wg, wgt, DD2);

    k_chunksum<<<(BB * NCH * DD) / 256, 256>>>(inputs);
    k_scan<<<(BB * DD) / 256, 256>>>();
    k_apply<<<(BB * NCH * DD) / 256, 256>>>(inputs);
    k_ln<<<MM, 256>>>(lng, lnb);

    dim3 grid12(DD / 128, MM / 128);     // (8, 256)
    k_gemm_h<0, DD, DD><<<grid12, 256, GEMM_SMEM>>>(hh, hh, w1t, b1, nullptr,
                                                    nullptr, interh);
    k_gemm_h<1, DD, DD><<<grid12, 256, GEMM_SMEM>>>(interh, interh, w2t, b2, avg,
                                                    avgout, avgouth);

    dim3 grid3(DD2 / 128, MM / 128);     // (16, 256)
    k_gemm_h<2, DD2, DD2><<<grid3, 256, GEMM_SMEM>>>(inh, avgouth, wgt, bg,
                                                     nullptr, nullptr, gatesh);

    k_final<<<((size_t)MM * DD / 4) / 256, 256>>>(inputs, out);
}

// round 8
// speedup vs baseline: 2.1805x; 1.0068x over previous
#include <cuda_runtime.h>
#include <cuda_fp16.h>
#include <math.h>
#include <stdint.h>

#define BB 8
#define LL 4096
#define DD 1024
#define MM (BB * LL)          // 32768 rows
#define DD2 (2 * DD)          // 2048
#define NCH 32
#define CHUNK (LL / NCH)      // 128

// ---------------- scratch (device globals; no allocation allowed) ----------
__device__ float  g_avg[(size_t)MM * DD];      // cumulative mean (fp32)
__device__ float  g_avgout[(size_t)MM * DD];   // inter@w2+b2+avg (fp32)
__device__ __half g_h_h[(size_t)MM * DD];      // layernorm(avg), fp16
__device__ __half g_inter_h[(size_t)MM * DD];  // relu(h@w1+b1), fp16
__device__ __half g_avgout_h[(size_t)MM * DD]; // fp16 copy of avgout
__device__ __half g_in_h[(size_t)MM * DD];     // fp16 inputs
__device__ __half g_gates_h[(size_t)MM * DD2]; // concat@wg+bg, fp16
__device__ float  g_csum[BB * NCH * DD];       // chunk partial sums
__device__ __half g_w1t[DD * DD];              // w1^T [N][K], fp16
__device__ __half g_w2t[DD * DD];
__device__ __half g_wgt[(size_t)DD2 * DD2];

// ---------------- helpers ----------------------------------------------------
__device__ __forceinline__ float sigf(float x) { return 1.f / (1.f + __expf(-x)); }

#define CP_ASYNC16(dst, src) \
    asm volatile("cp.async.cg.shared.global [%0], [%1], 16;" \
                 :: "r"(dst), "l"(src) : "memory")
#define CP_COMMIT() asm volatile("cp.async.commit_group;" ::: "memory")

#define MMA_F16(c, a0, a1, a2, a3, b0, b1)                                    \
    asm volatile(                                                             \
        "mma.sync.aligned.m16n8k16.row.col.f32.f16.f16.f32 "                  \
        "{%0,%1,%2,%3}, {%4,%5,%6,%7}, {%8,%9}, {%0,%1,%2,%3};"               \
        : "+f"((c)[0]), "+f"((c)[1]), "+f"((c)[2]), "+f"((c)[3])              \
        : "r"(a0), "r"(a1), "r"(a2), "r"(a3), "r"(b0), "r"(b1))

#define LDSM_X4(r0, r1, r2, r3, addr)                                         \
    asm volatile("ldmatrix.sync.aligned.m8n8.x4.shared.b16 {%0,%1,%2,%3}, [%4];" \
                 : "=r"(r0), "=r"(r1), "=r"(r2), "=r"(r3) : "r"(addr))

// ---------------- phase 1: chunked cumulative sum --------------------------
__global__ void __launch_bounds__(256) k_chunksum(const float* __restrict__ in) {
    int idx = blockIdx.x * blockDim.x + threadIdx.x;
    int d = idx & (DD - 1);
    int chunk = (idx >> 10) & (NCH - 1);
    int b = idx >> 15;
    const float* p = in + ((size_t)(b * LL + chunk * CHUNK)) * DD + d;
    float s = 0.f;
#pragma unroll 4
    for (int l = 0; l < CHUNK; ++l) s += p[(size_t)l * DD];
    g_csum[(b * NCH + chunk) * DD + d] = s;
}

__global__ void __launch_bounds__(256) k_scan() {
    int idx = blockIdx.x * blockDim.x + threadIdx.x;
    int d = idx & (DD - 1);
    int b = idx >> 10;
    float run = 0.f;
#pragma unroll
    for (int c = 0; c < NCH; ++c) {
        int o = (b * NCH + c) * DD + d;
        float t = g_csum[o];
        g_csum[o] = run;
        run += t;
    }
}

__global__ void __launch_bounds__(256) k_apply(const float* __restrict__ in) {
    int idx = blockIdx.x * blockDim.x + threadIdx.x;
    int d = idx & (DD - 1);
    int chunk = (idx >> 10) & (NCH - 1);
    int b = idx >> 15;
    size_t base = ((size_t)(b * LL + chunk * CHUNK)) * DD + d;
    const float* p = in + base;
    float* q = g_avg + base;
    __half* qh = g_in_h + base;
    float run = g_csum[(b * NCH + chunk) * DD + d];
    int l0 = chunk * CHUNK;
#pragma unroll 4
    for (int l = 0; l < CHUNK; ++l) {
        float v = p[(size_t)l * DD];
        run += v;
        q[(size_t)l * DD] = run / (float)(l0 + l + 1);
        qh[(size_t)l * DD] = __float2half_rn(v);
    }
}

// ---------------- phase 2: layernorm over D per row (fp16 out) ---------------
__global__ void __launch_bounds__(256) k_ln(const float* __restrict__ lng,
                                            const float* __restrict__ lnb) {
    int row = blockIdx.x;
    int t = threadIdx.x;
    const float4* x4 = reinterpret_cast<const float4*>(g_avg + (size_t)row * DD);
    float4 a = x4[t];
    float s = a.x + a.y + a.z + a.w;
    float ss = a.x * a.x + a.y * a.y + a.z * a.z + a.w * a.w;
#pragma unroll
    for (int o = 16; o > 0; o >>= 1) {
        s  += __shfl_xor_sync(0xffffffffu, s, o);
        ss += __shfl_xor_sync(0xffffffffu, ss, o);
    }
    __shared__ float sm[16];
    int w = t >> 5;
    if ((t & 31) == 0) { sm[w] = s; sm[8 + w] = ss; }
    __syncthreads();
    if (t < 32) {
        float v1 = (t < 8) ? sm[t] : 0.f;
        float v2 = (t < 8) ? sm[8 + t] : 0.f;
#pragma unroll
        for (int o = 4; o > 0; o >>= 1) {
            v1 += __shfl_xor_sync(0xffffffffu, v1, o);
            v2 += __shfl_xor_sync(0xffffffffu, v2, o);
        }
        if (t == 0) { sm[0] = v1; sm[1] = v2; }
    }
    __syncthreads();
    float mean = sm[0] * (1.f / DD);
    float var  = sm[1] * (1.f / DD) - mean * mean;
    float inv  = rsqrtf(var + 1e-6f);
    float4 g = reinterpret_cast<const float4*>(lng)[t];
    float4 b = reinterpret_cast<const float4*>(lnb)[t];
    __half2 h0 = __floats2half2_rn((a.x - mean) * inv * g.x + b.x,
                                   (a.y - mean) * inv * g.y + b.y);
    __half2 h1 = __floats2half2_rn((a.z - mean) * inv * g.z + b.z,
                                   (a.w - mean) * inv * g.w + b.w);
    __half2* dst = reinterpret_cast<__half2*>(g_h_h + (size_t)row * DD);
    dst[t * 2 + 0] = h0;
    dst[t * 2 + 1] = h1;
}

// ---------------- weight transpose (fp16 out): Wt[n][k] = W[k][n] ------------
__global__ void __launch_bounds__(256) k_transpose(const float* __restrict__ W,
                                                   __half* __restrict__ Wt, int N) {
    __shared__ float t[32][33];
    int bx = blockIdx.x * 32, by = blockIdx.y * 32;
    int x = bx + threadIdx.x;
#pragma unroll
    for (int i = 0; i < 32; i += 8)
        t[threadIdx.y + i][threadIdx.x] = W[(size_t)(by + threadIdx.y + i) * N + x];
    __syncthreads();
    int x2 = by + threadIdx.x;
#pragma unroll
    for (int i = 0; i < 32; i += 8)
        Wt[(size_t)(bx + threadIdx.y + i) * N + x2] =
            __float2half_rn(t[threadIdx.x][threadIdx.y + i]);
}

// ---------------- phase 3: fp16 mma.sync GEMM, 3-stage, 1 sync/iter ----------
// C[M,NN] = concatA[M,KTOT] @ Wt[NN,KTOT]^T (fp16 operands, fp32 accum).
// CTA tile 128x128, BK=64 halves, 8 warps (2x4), warp tile 64x32, m16n8k16.
// ldmatrix.x4 fragments; 3-stage cp.async pipeline, single barrier per iter.
// MODE 0: relu(x+b) -> Ch   MODE 1: x+b+add -> Cf + fp16 Ch   MODE 2: x+b -> Ch
#define LDPH 72
#define TILE_H (128 * LDPH)               // halves per tile
#define STG_H (2 * TILE_H)                // A + B per stage
#define GEMM_SMEM (3 * STG_H * 2)         // 3 stages = 110592 B

template <int MODE, int KTOT, int NN>
__global__ void __launch_bounds__(256, 2) k_gemm_h(
    const __half* __restrict__ A0, const __half* __restrict__ A1,
    const __half* __restrict__ Wt, const float* __restrict__ bias,
    const float* __restrict__ add, float* __restrict__ Cf,
    __half* __restrict__ Ch) {
    extern __shared__ __half smh[];
    int tid = threadIdx.x;
    int wid = tid >> 5, lane = tid & 31;
    int g = lane >> 2, tg = lane & 3;
    int wm = wid >> 2, wn = wid & 3;       // 2 x 4 warp grid
    int bm = blockIdx.y * 128, bn = blockIdx.x * 128;

    // per-lane ldmatrix offsets (in halves, within tile)
    int la_off = (lane & 15) * LDPH + (lane >> 4) * 8;                 // A x4
    int qb = lane >> 3;
    int lb_off = ((lane & 7) + (qb >> 1) * 8) * LDPH + (qb & 1) * 8;   // B x4

    float acc[16][4];
#pragma unroll
    for (int i = 0; i < 16; ++i)
#pragma unroll
        for (int j = 0; j < 4; ++j) acc[i][j] = 0.f;

    const int NK = KTOT / 64;

#define LOAD_STAGE(s, kk_)                                                     \
    {                                                                          \
        int kk = (kk_);                                                        \
        const __half* Ab = A0; int kloc = kk;                                  \
        if (KTOT > DD && kk >= DD) { Ab = A1; kloc = kk - DD; }                \
        __half* As = smh + (s) * STG_H;                                        \
        __half* Bs = As + TILE_H;                                              \
        _Pragma("unroll")                                                      \
        for (int it = 0; it < 4; ++it) {                                       \
            int i = tid + it * 256;                                            \
            int r = i >> 3, c = (i & 7) << 3;                                  \
            uint32_t da = (uint32_t)__cvta_generic_to_shared(As + r * LDPH + c); \
            CP_ASYNC16(da, Ab + (size_t)(bm + r) * DD + kloc + c);             \
            uint32_t db = (uint32_t)__cvta_generic_to_shared(Bs + r * LDPH + c); \
            CP_ASYNC16(db, Wt + (size_t)(bn + r) * KTOT + kk + c);             \
        }                                                                      \
    }

    LOAD_STAGE(0, 0);
    CP_COMMIT();
    LOAD_STAGE(1, 64);
    CP_COMMIT();

    int cur = 0;
    for (int kt = 0; kt < NK; ++kt) {
        if (kt + 1 < NK) {
            asm volatile("cp.async.wait_group 1;" ::: "memory");
        } else {
            asm volatile("cp.async.wait_group 0;" ::: "memory");
        }
        __syncthreads();
        if (kt + 2 < NK) {
            int nxt = cur + 2; if (nxt >= 3) nxt -= 3;
            LOAD_STAGE(nxt, (kt + 2) * 64);
            CP_COMMIT();
        }

        const __half* As = smh + cur * STG_H;
        const __half* Bs = As + TILE_H;
        uint32_t aB = (uint32_t)__cvta_generic_to_shared(
            As + (size_t)(wm * 64) * LDPH + la_off);
        uint32_t bB = (uint32_t)__cvta_generic_to_shared(
            Bs + (size_t)(wn * 32) * LDPH + lb_off);
#pragma unroll
        for (int kc = 0; kc < 4; ++kc) {
            int kb2 = kc * 32;                       // byte offset of k16 chunk
            uint32_t af[4][4], bf[4][2];
#pragma unroll
            for (int mt = 0; mt < 4; ++mt)
                LDSM_X4(af[mt][0], af[mt][1], af[mt][2], af[mt][3],
                        aB + mt * (16 * LDPH * 2) + kb2);
#pragma unroll
            for (int p = 0; p < 2; ++p)
                LDSM_X4(bf[p * 2][0], bf[p * 2][1], bf[p * 2 + 1][0],
                        bf[p * 2 + 1][1], bB + p * (16 * LDPH * 2) + kb2);
#pragma unroll
            for (int mt = 0; mt < 4; ++mt)
#pragma unroll
                for (int nt = 0; nt < 4; ++nt)
                    MMA_F16(acc[mt * 4 + nt], af[mt][0], af[mt][1], af[mt][2],
                            af[mt][3], bf[nt][0], bf[nt][1]);
        }
        ++cur; if (cur >= 3) cur = 0;
    }

#pragma unroll
    for (int mt = 0; mt < 4; ++mt) {
#pragma unroll
        for (int nt = 0; nt < 4; ++nt) {
            float* c = acc[mt * 4 + nt];
            int col = bn + wn * 32 + nt * 8 + 2 * tg;
            float2 bb = *reinterpret_cast<const float2*>(bias + col);
#pragma unroll
            for (int hh = 0; hh < 2; ++hh) {
                int row = bm + wm * 64 + mt * 16 + g + hh * 8;
                size_t off = (size_t)row * NN + col;
                float vx = c[hh * 2 + 0] + bb.x;
                float vy = c[hh * 2 + 1] + bb.y;
                if (MODE == 0) {
                    *reinterpret_cast<__half2*>(Ch + off) =
                        __floats2half2_rn(fmaxf(vx, 0.f), fmaxf(vy, 0.f));
                } else if (MODE == 1) {
                    float2 ad = *reinterpret_cast<const float2*>(add + off);
                    vx += ad.x; vy += ad.y;
                    float2 o; o.x = vx; o.y = vy;
                    *reinterpret_cast<float2*>(Cf + off) = o;
                    *reinterpret_cast<__half2*>(Ch + off) = __floats2half2_rn(vx, vy);
                } else {
                    *reinterpret_cast<__half2*>(Ch + off) = __floats2half2_rn(vx, vy);
                }
            }
        }
    }
#undef LOAD_STAGE
}

// ---------------- phase 4: gate combine --------------------------------------
__global__ void __launch_bounds__(256) k_final(const float* __restrict__ in,
                                               float* __restrict__ out) {
    int idx = blockIdx.x * blockDim.x + threadIdx.x;   // over M*D/4
    int row = idx >> 8;                                 // D/4 = 256
    int d4 = idx & 255;
    float4 i4 = reinterpret_cast<const float4*>(in)[idx];
    float4 a4 = reinterpret_cast<const float4*>(g_avgout)[idx];
    const __half2* gr = reinterpret_cast<const __half2*>(
        g_gates_h + (size_t)row * DD2);
    __half2 g1a = gr[d4 * 2 + 0];
    __half2 g1b = gr[d4 * 2 + 1];
    __half2 g2a = gr[512 + d4 * 2 + 0];
    __half2 g2b = gr[512 + d4 * 2 + 1];
    float4 o;
    o.x = sigf(__low2float(g1a))  * i4.x + sigf(__low2float(g2a))  * a4.x;
    o.y = sigf(__high2float(g1a)) * i4.y + sigf(__high2float(g2a)) * a4.y;
    o.z = sigf(__low2float(g1b))  * i4.z + sigf(__low2float(g2b))  * a4.z;
    o.w = sigf(__high2float(g1b)) * i4.w + sigf(__high2float(g2b)) * a4.w;
    reinterpret_cast<float4*>(out)[idx] = o;
}

// ---------------- launch -----------------------------------------------------
extern "C" void kernel_launch(void* const* d_in, const int* in_sizes, int n_in,
                              void* d_out, int out_size) {
    const float* inputs = (const float*)d_in[0];
    const float* w1 = (const float*)d_in[1];
    const float* b1 = (const float*)d_in[2];
    const float* w2 = (const float*)d_in[3];
    const float* b2 = (const float*)d_in[4];
    const float* lng = (const float*)d_in[5];
    const float* lnb = (const float*)d_in[6];
    const float* wg = (const float*)d_in[7];
    const float* bg = (const float*)d_in[8];
    float* out = (float*)d_out;

    float *avg, *avgout;
    __half *hh, *interh, *avgouth, *inh, *gatesh, *w1t, *w2t, *wgt;
    cudaGetSymbolAddress((void**)&avg, g_avg);
    cudaGetSymbolAddress((void**)&avgout, g_avgout);
    cudaGetSymbolAddress((void**)&hh, g_h_h);
    cudaGetSymbolAddress((void**)&interh, g_inter_h);
    cudaGetSymbolAddress((void**)&avgouth, g_avgout_h);
    cudaGetSymbolAddress((void**)&inh, g_in_h);
    cudaGetSymbolAddress((void**)&gatesh, g_gates_h);
    cudaGetSymbolAddress((void**)&w1t, g_w1t);
    cudaGetSymbolAddress((void**)&w2t, g_w2t);
    cudaGetSymbolAddress((void**)&wgt, g_wgt);

    cudaFuncSetAttribute(k_gemm_h<0, DD, DD>,
                         cudaFuncAttributeMaxDynamicSharedMemorySize, GEMM_SMEM);
    cudaFuncSetAttribute(k_gemm_h<1, DD, DD>,
                         cudaFuncAttributeMaxDynamicSharedMemorySize, GEMM_SMEM);
    cudaFuncSetAttribute(k_gemm_h<2, DD2, DD2>,
                         cudaFuncAttributeMaxDynamicSharedMemorySize, GEMM_SMEM);

    dim3 tb(32, 8);
    k_transpose<<<dim3(DD / 32, DD / 32), tb>>>(w1, w1t, DD);
    k_transpose<<<dim3(DD / 32, DD / 32), tb>>>(w2, w2t, DD);
    k_transpose<<<dim3(DD2 / 32, DD2 / 32), tb>>>(wg, wgt, DD2);

    k_chunksum<<<(BB * NCH * DD) / 256, 256>>>(inputs);
    k_scan<<<(BB * DD) / 256, 256>>>();
    k_apply<<<(BB * NCH * DD) / 256, 256>>>(inputs);
    k_ln<<<MM, 256>>>(lng, lnb);

    dim3 grid12(DD / 128, MM / 128);     // (8, 256)
    k_gemm_h<0, DD, DD><<<grid12, 256, GEMM_SMEM>>>(hh, hh, w1t, b1, nullptr,
                                                    nullptr, interh);
    k_gemm_h<1, DD, DD><<<grid12, 256, GEMM_SMEM>>>(interh, interh, w2t, b2, avg,
                                                    avgout, avgouth);

    dim3 grid3(DD2 / 128, MM / 128);     // (16, 256)
    k_gemm_h<2, DD2, DD2><<<grid3, 256, GEMM_SMEM>>>(inh, avgouth, wgt, bg,
                                                     nullptr, nullptr, gatesh);

    k_final<<<((size_t)MM * DD / 4) / 256, 256>>>(inputs, out);
}